// round 8
// baseline (speedup 1.0000x reference)
#include <cuda_runtime.h>

// 3-layer LSTM (H=48) over T=262144, batch 1, + PReLU/Linear/tanh head.
//
// R7: software-pipelined layers. One persistent CTA, 960 threads in 3 groups:
//   group0: threads [0,192)   -> layer 0, 1 thread per gate row (48-wide hh dot)
//   group1: threads [192,576) -> layer 1, 2 threads per row (24+24 halves, shfl combine)
//   group2: threads [576,960) -> layer 2, same
// Timestep skew: at iteration k, group l processes t = k - l. Only 2
// __syncthreads per iteration (gates ready / h ready).
// The input projection z0[t] = W_ih0 @ x_t + b_ih0 + b_hh0 is precomputed for
// all t by a parallel pre-pass kernel into a 201MB __device__ buffer and
// prefetched 2 iterations ahead inside the sequential kernel.

typedef unsigned long long ull;

#define HN    48
#define GATES 192
#define NT    960
#define TMAX  262144

__device__ float g_z[(size_t)TMAX * GATES];   // precomputed layer-0 input projection (+biases)

__device__ __forceinline__ void fma2(ull &acc, ull a, ull b) {
    asm("fma.rn.f32x2 %0, %1, %2, %0;" : "+l"(acc) : "l"(a), "l"(b));
}
__device__ __forceinline__ float pairsum(ull a) {
    return __int_as_float((unsigned)a) + __int_as_float((unsigned)(a >> 32));
}
// sigmoid(x) = 1/(1+2^(-x*log2(e)))
__device__ __forceinline__ float sigm(float x) {
    float e; asm("ex2.approx.f32 %0, %1;" : "=f"(e) : "f"(-1.4426950408889634f * x));
    float r; asm("rcp.approx.f32 %0, %1;" : "=f"(r) : "f"(1.0f + e));
    return r;
}
// tanh(x) = 1 - 2/(1+e^(2x))
__device__ __forceinline__ float tanh_(float x) {
    float e; asm("ex2.approx.f32 %0, %1;" : "=f"(e) : "f"(2.8853900817779268f * x));
    float r; asm("rcp.approx.f32 %0, %1;" : "=f"(r) : "f"(1.0f + e));
    return fmaf(-2.0f, r, 1.0f);
}

// ---------------- pre-pass: z0[t][g] = W_ih0[g]@x_t + b_ih0[g] + b_hh0[g] ----------------
__global__ void zprep_kernel(const float* __restrict__ x, int T,
                             const float* __restrict__ Wih0,
                             const float* __restrict__ bih0,
                             const float* __restrict__ bhh0)
{
    int t = blockIdx.x;
    if (t >= T) return;
    int g = threadIdx.x;                      // 0..191
    const float* xr = x + t * 5;
    const float* w  = Wih0 + g * 5;
    float acc = bih0[g] + bhh0[g];
    acc = fmaf(w[0], xr[0], acc);
    acc = fmaf(w[1], xr[1], acc);
    acc = fmaf(w[2], xr[2], acc);
    acc = fmaf(w[3], xr[3], acc);
    acc = fmaf(w[4], xr[4], acc);
    g_z[(size_t)t * GATES + g] = acc;
}

// ---------------- sequential pipelined LSTM ----------------
__global__ __launch_bounds__(NT, 1)
void lstm3_pipe(const float* __restrict__ Whh0,
                const float* __restrict__ Wih1, const float* __restrict__ Whh1,
                const float* __restrict__ bih1, const float* __restrict__ bhh1,
                const float* __restrict__ Wih2, const float* __restrict__ Whh2,
                const float* __restrict__ bih2, const float* __restrict__ bhh2,
                const float* __restrict__ prelu_a,
                const float* __restrict__ l1W, const float* __restrict__ l1b,
                const float* __restrict__ l2W, const float* __restrict__ l2b,
                float* __restrict__ out, int T)
{
    __shared__ __align__(16) float s_h[3][HN];     // h_{l} (single-buffered; phases separate R/W)
    __shared__ __align__(16) float s_gate[3][GATES];

    const int tid = threadIdx.x;
    const int grp = (tid < GATES) ? 0 : ((tid < 3 * GATES) ? 1 : 2);
    const int u   = tid - grp * GATES - (grp == 2 ? GATES : 0); // local idx: grp0:0..191, grp1/2:0..383
    // row/half decomposition
    int row, half;
    if (grp == 0) { row = u; half = 0; }
    else {
        int wg   = u >> 5;
        int lane = u & 31;
        half = lane >> 4;
        row  = wg * 16 + (lane & 15);
    }

    // ---- weights: every thread holds 48 floats = 12+12 ull ----
    // grp0 : wA = Whh0[row][0:24),  wB = Whh0[row][24:48)
    // grp1 : wA = Wih1[row][half*24 ..+24), wB = Whh1[row][half*24 ..+24)
    // grp2 : same with layer-2 weights
    ull wA[12], wB[12];
    float bias = 0.0f;
    if (grp == 0) {
        const ull* p = (const ull*)(Whh0 + row * 48);
        #pragma unroll
        for (int q = 0; q < 12; q++) wA[q] = p[q];
        #pragma unroll
        for (int q = 0; q < 12; q++) wB[q] = p[12 + q];
    } else {
        const float* Wih = (grp == 1) ? Wih1 : Wih2;
        const float* Whh = (grp == 1) ? Whh1 : Whh2;
        const ull* p = (const ull*)(Wih + row * 48 + half * 24);
        #pragma unroll
        for (int q = 0; q < 12; q++) wA[q] = p[q];
        p = (const ull*)(Whh + row * 48 + half * 24);
        #pragma unroll
        for (int q = 0; q < 12; q++) wB[q] = p[q];
        if (half == 0)
            bias = ((grp == 1) ? bih1[row] + bhh1[row] : bih2[row] + bhh2[row]);
    }

    // input-vector pointers for the two 24-wide partial dots
    const ulonglong2* hbp;   // "below" input half (grp0: h0[0:24))
    const ulonglong2* hop;   // "own"   input half (grp0: h0[24:48))
    if (grp == 0) {
        hbp = (const ulonglong2*)&s_h[0][0];
        hop = (const ulonglong2*)&s_h[0][24];
    } else if (grp == 1) {
        hbp = (const ulonglong2*)&s_h[0][half * 24];
        hop = (const ulonglong2*)&s_h[1][half * 24];
    } else {
        hbp = (const ulonglong2*)&s_h[1][half * 24];
        hop = (const ulonglong2*)&s_h[2][half * 24];
    }

    // activation selector (rows [96,144) = tanh 'g' gate), branch-free
    const bool  is_g = (row >= 96 && row < 144);
    const float aSc  = is_g ? 2.0f : 1.0f;
    const float aMul = is_g ? 2.0f : 1.0f;
    const float aAdd = is_g ? -1.0f : 0.0f;

    // init shared
    if (tid < 3 * HN) (&s_h[0][0])[tid] = 0.0f;

    const int Tm1 = T - 1;
    float c = 0.0f;                       // cell state (threads u<48 of each group)
    float znew = 0.0f;
    // z prefetch registers (grp0 only): z0r for even k, z1r for odd k
    float z0r = 0.0f, z1r = 0.0f;
    if (grp == 0) {
        z0r = g_z[row];
        z1r = g_z[(T > 1 ? GATES : 0) + row];
    }

    __syncthreads();

    auto step = [&](int kk, float& zcur) {
        // ---------------- phase A: gate computation ----------------
        ull a0 = 0ull, a1 = 0ull;
        #pragma unroll
        for (int q = 0; q < 6; q++) {
            ulonglong2 v = hbp[q];
            fma2(a0, wA[2 * q], v.x);
            fma2(a1, wA[2 * q + 1], v.y);
        }
        #pragma unroll
        for (int q = 0; q < 6; q++) {
            ulonglong2 v = hop[q];
            fma2(a0, wB[2 * q], v.x);
            fma2(a1, wB[2 * q + 1], v.y);
        }
        float p = pairsum(a0) + pairsum(a1);
        if (grp == 0) {
            float gs = p + zcur;                       // bias already folded into z
            float sv = sigm(aSc * gs);
            s_gate[0][row] = fmaf(aMul, sv, aAdd);
            int kp = kk + 2; if (kp > Tm1) kp = Tm1;   // prefetch z[k+2]
            znew = g_z[kp * GATES + row];
        } else {
            p += __shfl_xor_sync(0xffffffffu, p, 16);  // combine halves, no barrier
            if (half == 0) {
                float gs = p + bias;
                float sv = sigm(aSc * gs);
                s_gate[grp][row] = fmaf(aMul, sv, aAdd);
            }
        }
        __syncthreads();                               // B1: gates ready
        // ---------------- phase B: cell/hidden update ----------------
        {
            int tg = kk - grp;                         // this group's timestep
            if (u < HN && (unsigned)tg < (unsigned)T) {
                float gi = s_gate[grp][u];
                float gf = s_gate[grp][HN + u];
                float gg = s_gate[grp][2 * HN + u];
                float go = s_gate[grp][3 * HN + u];
                c = fmaf(gf, c, gi * gg);
                s_h[grp][u] = go * tanh_(c);
            }
        }
        __syncthreads();                               // B2: h ready
        if (grp == 0) zcur = znew;
    };

    const int K = T + 2;                               // pipeline drain: 2 extra iterations
    for (int k = 0; k < K; k += 2) {
        step(k,     z0r);
        step(k + 1, z1r);
    }

    // ---- head: PReLU -> lin1 -> flatten -> lin2 -> tanh ----
    if (tid == 0) {
        float a = prelu_a[0];
        float v[6];
        #pragma unroll
        for (int l = 0; l < 3; l++) {
            #pragma unroll
            for (int kk = 0; kk < 2; kk++) {
                float acc = l1b[kk];
                #pragma unroll
                for (int j = 0; j < HN; j++) {
                    float hv = s_h[l][j];
                    hv = hv > 0.0f ? hv : a * hv;
                    acc = fmaf(hv, l1W[kk * HN + j], acc);
                }
                v[l * 2 + kk] = acc;
            }
        }
        #pragma unroll
        for (int kk = 0; kk < 2; kk++) {
            float acc = l2b[kk];
            #pragma unroll
            for (int m = 0; m < 6; m++) acc = fmaf(l2W[kk * 6 + m], v[m], acc);
            out[kk] = tanh_(acc);
        }
    }
}

extern "C" void kernel_launch(void* const* d_in, const int* in_sizes, int n_in,
                              void* d_out, int out_size) {
    int T = in_sizes[0] / 5;       // x is [1, T, 5]
    if (T > TMAX) T = TMAX;

    // pre-pass: parallel input projection across the whole chip
    zprep_kernel<<<T, GATES>>>(
        (const float*)d_in[0], T,
        (const float*)d_in[1],           // W_ih0
        (const float*)d_in[3],           // b_ih0
        (const float*)d_in[4]);          // b_hh0

    // sequential pipelined recurrence (single CTA)
    lstm3_pipe<<<1, NT>>>(
        (const float*)d_in[2],           // W_hh0
        (const float*)d_in[5],  (const float*)d_in[6],   // W_ih1, W_hh1
        (const float*)d_in[7],  (const float*)d_in[8],   // b_ih1, b_hh1
        (const float*)d_in[9],  (const float*)d_in[10],  // W_ih2, W_hh2
        (const float*)d_in[11], (const float*)d_in[12],  // b_ih2, b_hh2
        (const float*)d_in[13],                          // prelu_a
        (const float*)d_in[14], (const float*)d_in[15],  // lin1_W, lin1_b
        (const float*)d_in[16], (const float*)d_in[17],  // lin2_W, lin2_b
        (float*)d_out, T);
}

// round 9
// speedup vs baseline: 2.5610x; 2.5610x over previous
#include <cuda_runtime.h>

// 3-layer LSTM (H=48) over T=262144, batch 1, + PReLU/Linear/tanh head.
//
// R8: software-pipelined layers, register-balanced to avoid R7's spills.
// One persistent CTA, 480 threads (15 warps) in 3 groups:
//   grp0: threads [0,96)    -> layer 0, TWO gate rows per thread (48-wide hh dots)
//   grp1: threads [96,288)  -> layer 1, one row per thread (48 ih + 48 hh dot)
//   grp2: threads [288,480) -> layer 2, same
// Every thread carries exactly 48 ull (96 float) weights -> uniform ~120 regs,
// under the 136-reg cap at 480 threads. Two __syncthreads per iteration.
// Timestep skew: at iteration k, group l processes t = k - l.
// Input projection z0[t] = W_ih0 @ x_t + b_ih0 + b_hh0 precomputed by a
// parallel pre-pass into a __device__ buffer, prefetched 2 iterations ahead.

typedef unsigned long long ull;

#define HN    48
#define GATES 192
#define NT    480
#define TMAX  262144

__device__ float g_z[(size_t)TMAX * GATES];   // layer-0 input projection (+biases)

__device__ __forceinline__ void fma2(ull &acc, ull a, ull b) {
    asm("fma.rn.f32x2 %0, %1, %2, %0;" : "+l"(acc) : "l"(a), "l"(b));
}
__device__ __forceinline__ float pairsum(ull a) {
    return __int_as_float((unsigned)a) + __int_as_float((unsigned)(a >> 32));
}
// sigmoid(x) = 1/(1+2^(-x*log2(e)))
__device__ __forceinline__ float sigm(float x) {
    float e; asm("ex2.approx.f32 %0, %1;" : "=f"(e) : "f"(-1.4426950408889634f * x));
    float r; asm("rcp.approx.f32 %0, %1;" : "=f"(r) : "f"(1.0f + e));
    return r;
}
// tanh(x) = 1 - 2/(1+e^(2x))
__device__ __forceinline__ float tanh_(float x) {
    float e; asm("ex2.approx.f32 %0, %1;" : "=f"(e) : "f"(2.8853900817779268f * x));
    float r; asm("rcp.approx.f32 %0, %1;" : "=f"(r) : "f"(1.0f + e));
    return fmaf(-2.0f, r, 1.0f);
}

// ---------------- pre-pass: z0[t][g] = W_ih0[g]@x_t + b_ih0[g] + b_hh0[g] ----------------
__global__ void zprep_kernel(const float* __restrict__ x, int T,
                             const float* __restrict__ Wih0,
                             const float* __restrict__ bih0,
                             const float* __restrict__ bhh0)
{
    int t = blockIdx.x;
    if (t >= T) return;
    int g = threadIdx.x;                      // 0..191
    const float* xr = x + t * 5;
    const float* w  = Wih0 + g * 5;
    float acc = bih0[g] + bhh0[g];
    acc = fmaf(w[0], xr[0], acc);
    acc = fmaf(w[1], xr[1], acc);
    acc = fmaf(w[2], xr[2], acc);
    acc = fmaf(w[3], xr[3], acc);
    acc = fmaf(w[4], xr[4], acc);
    g_z[(size_t)t * GATES + g] = acc;
}

// ---------------- sequential pipelined LSTM ----------------
__global__ __launch_bounds__(NT, 1)
void lstm3_pipe(const float* __restrict__ Whh0,
                const float* __restrict__ Wih1, const float* __restrict__ Whh1,
                const float* __restrict__ bih1, const float* __restrict__ bhh1,
                const float* __restrict__ Wih2, const float* __restrict__ Whh2,
                const float* __restrict__ bih2, const float* __restrict__ bhh2,
                const float* __restrict__ prelu_a,
                const float* __restrict__ l1W, const float* __restrict__ l1b,
                const float* __restrict__ l2W, const float* __restrict__ l2b,
                float* __restrict__ out, int T)
{
    __shared__ __align__(16) float s_h[3][HN];        // h_l (phases separate R/W)
    __shared__ __align__(16) float s_gate[3][GATES];  // activated gates per layer

    const int tid = threadIdx.x;
    const int grp = (tid < 96) ? 0 : ((tid < 288) ? 1 : 2);

    // ---- register-resident weights: every thread 48 ull = 96 floats ----
    ull wA[24], wB[24];
    float bias = 0.0f;
    int rowA = 0, rowB = 0, row = 0;

    const ulonglong2* hbp;   // input vector 1 (grp0: h0; grp1: h0; grp2: h1)
    const ulonglong2* hop;   // input vector 2 (grp1: h1; grp2: h2; grp0: unused)

    if (grp == 0) {
        rowA = tid;          // rows [0,96): i/f gates (always sigmoid)
        rowB = tid + 96;     // rows [96,192): g (tanh) if tid<48 else o (sigmoid)
        const ull* p = (const ull*)(Whh0 + rowA * 48);
        #pragma unroll
        for (int q = 0; q < 24; q++) wA[q] = p[q];
        p = (const ull*)(Whh0 + rowB * 48);
        #pragma unroll
        for (int q = 0; q < 24; q++) wB[q] = p[q];
        hbp = (const ulonglong2*)&s_h[0][0];
        hop = hbp;
    } else {
        row = tid - (grp == 1 ? 96 : 288);
        const float* Wih = (grp == 1) ? Wih1 : Wih2;
        const float* Whh = (grp == 1) ? Whh1 : Whh2;
        const ull* p = (const ull*)(Wih + row * 48);
        #pragma unroll
        for (int q = 0; q < 24; q++) wA[q] = p[q];
        p = (const ull*)(Whh + row * 48);
        #pragma unroll
        for (int q = 0; q < 24; q++) wB[q] = p[q];
        bias = (grp == 1) ? (bih1[row] + bhh1[row]) : (bih2[row] + bhh2[row]);
        hbp = (const ulonglong2*)&s_h[grp - 1][0];
        hop = (const ulonglong2*)&s_h[grp][0];
    }

    // branch-free activation selectors
    const bool  isg  = (grp != 0) && (row >= 96 && row < 144);  // grp1/2 tanh rows
    const float aSc  = isg ? 2.0f : 1.0f;
    const float aMul = isg ? 2.0f : 1.0f;
    const float aAdd = isg ? -1.0f : 0.0f;
    const bool  isgB = (grp == 0) && (tid < 48);                // grp0 second row = g gate
    const float bSc  = isgB ? 2.0f : 1.0f;
    const float bMul = isgB ? 2.0f : 1.0f;
    const float bAdd = isgB ? -1.0f : 0.0f;

    // cell-update local index: threads cu<48 of each group own c/h elements
    const int cu = (grp == 0) ? tid : row;

    if (tid < 3 * HN) (&s_h[0][0])[tid] = 0.0f;

    const int Tm1 = T - 1;
    float c = 0.0f;

    // z prefetch (grp0 only): two rows x two parities
    float zA0 = 0.f, zA1 = 0.f, zB0 = 0.f, zB1 = 0.f;
    float znA = 0.f, znB = 0.f;
    if (grp == 0) {
        zA0 = g_z[rowA];
        zB0 = g_z[rowB];
        int t1 = (T > 1) ? 1 : 0;
        zA1 = g_z[(size_t)t1 * GATES + rowA];
        zB1 = g_z[(size_t)t1 * GATES + rowB];
    }

    __syncthreads();

    auto step = [&](int kk, float& zA, float& zB) {
        // ---------------- phase A: gate matvecs + activations ----------------
        if (grp == 0) {
            ull a0 = 0ull, a1 = 0ull, b0 = 0ull, b1 = 0ull;
            #pragma unroll
            for (int q = 0; q < 12; q++) {
                ulonglong2 v = hbp[q];
                fma2(a0, wA[2 * q],     v.x);
                fma2(a1, wA[2 * q + 1], v.y);
                fma2(b0, wB[2 * q],     v.x);
                fma2(b1, wB[2 * q + 1], v.y);
            }
            float gA = pairsum(a0) + pairsum(a1) + zA;   // bias folded into z
            float gB = pairsum(b0) + pairsum(b1) + zB;
            s_gate[0][rowA] = sigm(gA);                  // i/f rows: plain sigmoid
            float sv = sigm(bSc * gB);
            s_gate[0][rowB] = fmaf(bMul, sv, bAdd);
            int kp = kk + 2; if (kp > Tm1) kp = Tm1;     // prefetch z[k+2]
            znA = g_z[(size_t)kp * GATES + rowA];
            znB = g_z[(size_t)kp * GATES + rowB];
        } else {
            ull a0 = 0ull, a1 = 0ull, b0 = 0ull, b1 = 0ull;
            #pragma unroll
            for (int q = 0; q < 12; q++) {
                ulonglong2 v = hbp[q];
                ulonglong2 w = hop[q];
                fma2(a0, wA[2 * q],     v.x);
                fma2(a1, wA[2 * q + 1], v.y);
                fma2(b0, wB[2 * q],     w.x);
                fma2(b1, wB[2 * q + 1], w.y);
            }
            float g = pairsum(a0) + pairsum(a1) + pairsum(b0) + pairsum(b1) + bias;
            float sv = sigm(aSc * g);
            s_gate[grp][row] = fmaf(aMul, sv, aAdd);
        }
        __syncthreads();                                 // B1: gates ready
        // ---------------- phase B: cell/hidden update ----------------
        {
            int tg = kk - grp;
            if (cu < HN && (unsigned)tg < (unsigned)T) {
                float gi = s_gate[grp][cu];
                float gf = s_gate[grp][HN + cu];
                float gg = s_gate[grp][2 * HN + cu];
                float go = s_gate[grp][3 * HN + cu];
                c = fmaf(gf, c, gi * gg);
                s_h[grp][cu] = go * tanh_(c);
            }
        }
        __syncthreads();                                 // B2: h ready
        if (grp == 0) { zA = znA; zB = znB; }
    };

    const int K = T + 2;                                 // pipeline drain
    for (int k = 0; k < K; k += 2) {
        step(k,     zA0, zB0);
        step(k + 1, zA1, zB1);
    }

    // ---- head: PReLU -> lin1 -> flatten -> lin2 -> tanh ----
    if (tid == 0) {
        float a = prelu_a[0];
        float v[6];
        #pragma unroll
        for (int l = 0; l < 3; l++) {
            #pragma unroll
            for (int kk = 0; kk < 2; kk++) {
                float acc = l1b[kk];
                #pragma unroll
                for (int j = 0; j < HN; j++) {
                    float hv = s_h[l][j];
                    hv = hv > 0.0f ? hv : a * hv;
                    acc = fmaf(hv, l1W[kk * HN + j], acc);
                }
                v[l * 2 + kk] = acc;
            }
        }
        #pragma unroll
        for (int kk = 0; kk < 2; kk++) {
            float acc = l2b[kk];
            #pragma unroll
            for (int m = 0; m < 6; m++) acc = fmaf(l2W[kk * 6 + m], v[m], acc);
            out[kk] = tanh_(acc);
        }
    }
}

extern "C" void kernel_launch(void* const* d_in, const int* in_sizes, int n_in,
                              void* d_out, int out_size) {
    int T = in_sizes[0] / 5;       // x is [1, T, 5]
    if (T > TMAX) T = TMAX;

    // pre-pass: parallel input projection across the whole chip
    zprep_kernel<<<T, GATES>>>(
        (const float*)d_in[0], T,
        (const float*)d_in[1],           // W_ih0
        (const float*)d_in[3],           // b_ih0
        (const float*)d_in[4]);          // b_hh0

    // sequential pipelined recurrence (single CTA)
    lstm3_pipe<<<1, NT>>>(
        (const float*)d_in[2],           // W_hh0
        (const float*)d_in[5],  (const float*)d_in[6],   // W_ih1, W_hh1
        (const float*)d_in[7],  (const float*)d_in[8],   // b_ih1, b_hh1
        (const float*)d_in[9],  (const float*)d_in[10],  // W_ih2, W_hh2
        (const float*)d_in[11], (const float*)d_in[12],  // b_ih2, b_hh2
        (const float*)d_in[13],                          // prelu_a
        (const float*)d_in[14], (const float*)d_in[15],  // lin1_W, lin1_b
        (const float*)d_in[16], (const float*)d_in[17],  // lin2_W, lin2_b
        (float*)d_out, T);
}